// round 11
// baseline (speedup 1.0000x reference)
#include <cuda_runtime.h>
#include <cuda_bf16.h>

#define GD 128
#define RB 66                         // brick coords 0..65 cover x0 in [-2..128]
#define BRICKS (RB * RB * RB)         // 287,496 bricks per replica
#define TOTAL_BRICKS (8 * BRICKS)     // 8 parity replicas
#define CELLS (GD * GD * GD)
// Each brick = 2x2x2 cells as bf16 = 16 bytes.
// Zero-initialized at load; huber_zero_kernel re-zeroes every slot it reads,
// so the read-region invariant holds across graph replays. Padding slots may
// accumulate garbage but are never read.
__device__ uint4 g_rep[TOTAL_BRICKS];

__device__ __forceinline__ unsigned pack_bf16x2(float lo, float hi) {
    unsigned u;
    asm("cvt.rn.bf16x2.f32 %0, %1, %2;" : "=r"(u) : "f"(hi), "f"(lo));
    return u;
}

__device__ __forceinline__ void red_add_v4_bf16x2(void* addr, unsigned a,
                                                  unsigned b, unsigned c,
                                                  unsigned d) {
    asm volatile("red.global.add.noftz.v4.bf16x2 [%0], {%1, %2, %3, %4};"
                 :: "l"(addr), "r"(a), "r"(b), "r"(c), "r"(d) : "memory");
}

// ---------------------------------------------------------------------------
// One splat = ONE v4.bf16x2 red: replica (x0&1,y0&1,z0&1) makes the 2x2x2
// corner cube one aligned 16B brick. Lane idx = lz*4 + ly*2 + lx.
// ---------------------------------------------------------------------------
__device__ __forceinline__ void splat_one(float cx, float cy, float cz,
                                          float sign) {
    const float x = fmaf(cx, 64.0f, 63.5f);   // ((c+1)*128-1)/2
    const float y = fmaf(cy, 64.0f, 63.5f);
    const float z = fmaf(cz, 64.0f, 63.5f);

    const float x0f = floorf(x), y0f = floorf(y), z0f = floorf(z);
    const float fx = x - x0f, fy = y - y0f, fz = z - z0f;
    int x0 = (int)x0f, y0 = (int)y0f, z0 = (int)z0f;
    // Far-out points clamp into the padded range; OOB corners land in padding
    // slots the huber gather never reads (and never zeroes — harmless).
    x0 = max(-2, min(128, x0));
    y0 = max(-2, min(128, y0));
    z0 = max(-2, min(128, z0));

    const float wx0 = 1.0f - fx, wx1 = fx;
    const float wy0 = 1.0f - fy, wy1 = fy;
    const float wz0 = (1.0f - fz) * sign, wz1 = fz * sign;

    const int sx = x0 & 1, sy = y0 & 1, sz = z0 & 1;
    const int bx = (x0 + sx + 2) >> 1;
    const int by = (y0 + sy + 2) >> 1;
    const int bz = (z0 + sz + 2) >> 1;
    const int rep = (sz << 2) | (sy << 1) | sx;

    uint4* addr = g_rep + (size_t)rep * BRICKS
                + ((size_t)bz * RB + by) * RB + bx;

    const float a00 = wx0 * wy0, a10 = wx1 * wy0;
    const float a01 = wx0 * wy1, a11 = wx1 * wy1;

    red_add_v4_bf16x2(addr,
        pack_bf16x2(a00 * wz0, a10 * wz0),
        pack_bf16x2(a01 * wz0, a11 * wz0),
        pack_bf16x2(a00 * wz1, a10 * wz1),
        pack_bf16x2(a01 * wz1, a11 * wz1));
}

// ---------------------------------------------------------------------------
// Splat: ONE point per thread (proven best occupancy/latency-hiding shape).
// ---------------------------------------------------------------------------
__global__ void splat_kernel(const float* __restrict__ pred,
                             const float* __restrict__ gt,
                             const float* __restrict__ coords,
                             int N, float* __restrict__ out) {
    const int p = blockIdx.x * blockDim.x + threadIdx.x;
    if (p == 0) *out = 0.f;      // huber (next kernel) accumulates into out
    if (p >= N) return;

    const float cx = coords[3 * p + 0];
    const float cy = coords[3 * p + 1];
    const float cz = coords[3 * p + 2];
    const float px = pred[3 * p + 0];
    const float py = pred[3 * p + 1];
    const float pz = pred[3 * p + 2];
    const float gx = gt[3 * p + 0];
    const float gy = gt[3 * p + 1];
    const float gz = gt[3 * p + 2];

    splat_one(cx + px, cy + py, cz + pz,  1.0f);
    splat_one(cx + gx, cy + gy, cz + gz, -1.0f);
}

// ---------------------------------------------------------------------------
// Fused huber + zero. 8 cells (one aligned x-octet) per thread.
// Per replica the octet's lanes live at one 4B sub-offset of 4 (sx=0) or
// 5 (sx=1) consecutive bricks -> 36 aligned bf16x2 loads per thread.
// The slot<->cell map is bijective: each uint is read by exactly one thread
// (sx=0) or shared only between x-adjacent threads in the SAME warp (sx=1
// boundary uints; a warp covers 2 complete 16-octet rows). So after a
// __syncwarp (memory-ordering barrier), each thread stores 0 back to every
// address it loaded: disjoint or identical-value stores -> deterministic.
// ---------------------------------------------------------------------------
#define HUB_THREADS 256

__global__ void huber_zero_kernel(float* __restrict__ out) {
    unsigned* __restrict__ gu = reinterpret_cast<unsigned*>(g_rep);
    const int t = blockIdx.x * HUB_THREADS + threadIdx.x;
    const int cell0 = t * 8;
    const int xx0 = cell0 & 127;            // even multiple of 8
    const int yy  = (cell0 >> 7) & 127;
    const int zz  = cell0 >> 14;
    const int B0  = (xx0 + 2) >> 1;

    unsigned uv[36];                        // 4 uints x 4 reps + 5 x 4 reps
    size_t  addr[36];

    int idx = 0;
    #pragma unroll
    for (int rep = 0; rep < 8; ++rep) {
        const int sx = rep & 1, sy = (rep >> 1) & 1, sz = rep >> 2;
        const int ly = (yy ^ sy) & 1;
        const int lz = (zz ^ sz) & 1;
        const int by = (yy - ly + sy + 2) >> 1;
        const int bz = (zz - lz + sz + 2) >> 1;
        const size_t brick0 = (size_t)rep * BRICKS
                            + ((size_t)bz * RB + by) * RB + B0;
        const int off = (lz << 1) | ly;     // uint within brick
        const int cnt = 4 + sx;             // 4 bricks (sx=0) or 5 (sx=1)
        #pragma unroll
        for (int k = 0; k < 5; ++k) {
            if (k < cnt) {
                const size_t a = (brick0 + k) * 4 + off;
                addr[idx] = a;
                uv[idx] = gu[a];
                ++idx;
            }
        }
    }

    // All 36 loads issued & values latched; order them before zero-stores.
    __syncwarp();

    #pragma unroll
    for (int k = 0; k < 36; ++k) gu[addr[k]] = 0u;

    // ---- huber math on the latched values ----
    float vc[8];
    #pragma unroll
    for (int j = 0; j < 8; ++j) vc[j] = 0.f;

    idx = 0;
    #pragma unroll
    for (int rep = 0; rep < 8; ++rep) {
        const int sx = rep & 1;
        if (sx == 0) {
            #pragma unroll
            for (int j = 0; j < 8; ++j) {
                const unsigned u = uv[idx + (j >> 1)];
                const __nv_bfloat162 b2 =
                    *reinterpret_cast<const __nv_bfloat162*>(&u);
                vc[j] += __bfloat162float((j & 1) ? b2.y : b2.x);
            }
            idx += 4;
        } else {
            #pragma unroll
            for (int j = 0; j < 8; ++j) {
                // j even -> hi half of u[j/2]; j odd -> lo half of u[(j+1)/2]
                const unsigned u = uv[idx + ((j + 1) >> 1)];
                const __nv_bfloat162 b2 =
                    *reinterpret_cast<const __nv_bfloat162*>(&u);
                vc[j] += __bfloat162float((j & 1) ? b2.x : b2.y);
            }
            idx += 5;
        }
    }

    float s = 0.f;
    #pragma unroll
    for (int j = 0; j < 8; ++j) {
        const float a = fabsf(vc[j]);
        s += (a <= 1.f) ? 0.5f * vc[j] * vc[j] : a - 0.5f;
    }

    #pragma unroll
    for (int o = 16; o; o >>= 1) s += __shfl_xor_sync(0xFFFFFFFFu, s, o);

    __shared__ float smem[8];
    const int lane = threadIdx.x & 31;
    const int warp = threadIdx.x >> 5;
    if (lane == 0) smem[warp] = s;
    __syncthreads();

    if (warp == 0) {
        s = (lane < (HUB_THREADS >> 5)) ? smem[lane] : 0.f;
        #pragma unroll
        for (int o = 4; o; o >>= 1) s += __shfl_xor_sync(0xFFFFFFFFu, s, o);
        if (lane == 0) atomicAdd(out, s);
    }
}

// ---------------------------------------------------------------------------
// Launch: splat -> fused huber+zero
// ---------------------------------------------------------------------------
extern "C" void kernel_launch(void* const* d_in, const int* in_sizes, int n_in,
                              void* d_out, int out_size) {
    const float* pred   = (const float*)d_in[0];  // registration_pred [1,N,3]
    const float* gt     = (const float*)d_in[1];  // registration_gt   [1,N,3]
    const float* coords = (const float*)d_in[2];  // coords            [1,N,3]
    float* out = (float*)d_out;

    const int N = in_sizes[0] / 3;

    {   // splat: one thread per point (pred +1, gt -1); also zeroes *out
        const int threads = 256;
        splat_kernel<<<(N + threads - 1) / threads, threads>>>(
            pred, gt, coords, N, out);
    }
    {   // fused huber gather + reduction + grid re-zero: 8 cells/thread
        const int nt = CELLS / 8;                  // 262,144 threads
        huber_zero_kernel<<<nt / HUB_THREADS, HUB_THREADS>>>(out);
    }
}